// round 8
// baseline (speedup 1.0000x reference)
#include <cuda_runtime.h>
#include <cstdint>

// Palette packed keys: (r<<16)|(g<<8)|b  -> class id == index
// 0: 0x000000  1: 0x800000  2: 0x804080  3: 0xC000C0
// 4: 0x008000  5: 0x808000  6: 0x404000  7: 0x400080

__device__ __forceinline__ float classify(int r, int g, int b) {
    unsigned key = ((unsigned)r << 16) | ((unsigned)g << 8) | (unsigned)b;
    int c = 0;
    c += (key == 0x800000u) ? 1 : 0;
    c += (key == 0x804080u) ? 2 : 0;
    c += (key == 0xC000C0u) ? 3 : 0;
    c += (key == 0x008000u) ? 4 : 0;
    c += (key == 0x808000u) ? 5 : 0;
    c += (key == 0x404000u) ? 6 : 0;
    c += (key == 0x400080u) ? 7 : 0;
    return (float)c;  // unmatched (incl. key 0) -> 0
}

__device__ __forceinline__ float4 classify4(int4 r, int4 g, int4 b) {
    float4 o;
    o.x = classify(r.x, g.x, b.x);
    o.y = classify(r.y, g.y, b.y);
    o.z = classify(r.z, g.z, b.z);
    o.w = classify(r.w, g.w, b.w);
    return o;
}

// Persistent single-wave kernel, unroll-4: 12 front-batched coalesced loads
// (192 B/thread in flight), then 4 contiguous stores. Maximizes read-burst
// length between store bursts to reduce HBM R/W turnaround frequency.
__global__ void __launch_bounds__(256)
uavid_persist4_kernel(const int4* __restrict__ rp,
                      const int4* __restrict__ gp,
                      const int4* __restrict__ bp,
                      float4* __restrict__ out,
                      int n4) {
    int s = gridDim.x * blockDim.x;
    int i = blockIdx.x * blockDim.x + threadIdx.x;
    int s4 = 4 * s;
    // Main unrolled loop: 4 quads per iteration at stride s apart.
    for (; i + 3 * s < n4; i += s4) {
        int i1 = i + s, i2 = i + 2 * s, i3 = i + 3 * s;
        int4 r0 = rp[i];  int4 r1 = rp[i1]; int4 r2 = rp[i2]; int4 r3 = rp[i3];
        int4 g0 = gp[i];  int4 g1 = gp[i1]; int4 g2 = gp[i2]; int4 g3 = gp[i3];
        int4 b0 = bp[i];  int4 b1 = bp[i1]; int4 b2 = bp[i2]; int4 b3 = bp[i3];
        out[i]  = classify4(r0, g0, b0);
        out[i1] = classify4(r1, g1, b1);
        out[i2] = classify4(r2, g2, b2);
        out[i3] = classify4(r3, g3, b3);
    }
    // Remainder
    for (; i < n4; i += s) {
        int4 r = rp[i];
        int4 g = gp[i];
        int4 b = bp[i];
        out[i] = classify4(r, g, b);
    }
}

__global__ void uavid_tail_f32_kernel(const int* __restrict__ rp,
                                      const int* __restrict__ gp,
                                      const int* __restrict__ bp,
                                      float* __restrict__ out,
                                      int start, int hw) {
    int i = start + blockIdx.x * blockDim.x + threadIdx.x;
    if (i >= hw) return;
    out[i] = classify(rp[i], gp[i], bp[i]);
}

extern "C" void kernel_launch(void* const* d_in, const int* in_sizes, int n_in,
                              void* d_out, int out_size) {
    const int* t = (const int*)d_in[0];
    int n  = in_sizes[0];     // 3 * H * W
    int hw = n / 3;           // H * W
    const int* rp = t;
    const int* gp = t + hw;
    const int* bp = t + 2 * hw;

    int n4  = hw >> 2;        // vectorized pixel-quads
    int rem = hw & 3;

    if (n4 > 0) {
        int threads = 256;
        int blocks = 148 * 8;   // one full wave
        int max_blocks = (n4 + threads - 1) / threads;
        if (blocks > max_blocks) blocks = max_blocks;
        uavid_persist4_kernel<<<blocks, threads>>>(
            (const int4*)rp, (const int4*)gp, (const int4*)bp,
            (float4*)d_out, n4);
    }
    if (rem > 0) {
        uavid_tail_f32_kernel<<<1, 256>>>(rp, gp, bp,
                                          (float*)d_out, n4 << 2, hw);
    }
}

// round 9
// speedup vs baseline: 1.0904x; 1.0904x over previous
#include <cuda_runtime.h>
#include <cstdint>

// Palette packed keys: (r<<16)|(g<<8)|b  -> class id == index
// 0: 0x000000  1: 0x800000  2: 0x804080  3: 0xC000C0
// 4: 0x008000  5: 0x808000  6: 0x404000  7: 0x400080

__device__ __forceinline__ float classify(int r, int g, int b) {
    unsigned key = ((unsigned)r << 16) | ((unsigned)g << 8) | (unsigned)b;
    int c = 0;
    c += (key == 0x800000u) ? 1 : 0;
    c += (key == 0x804080u) ? 2 : 0;
    c += (key == 0xC000C0u) ? 3 : 0;
    c += (key == 0x008000u) ? 4 : 0;
    c += (key == 0x808000u) ? 5 : 0;
    c += (key == 0x404000u) ? 6 : 0;
    c += (key == 0x400080u) ? 7 : 0;
    return (float)c;  // unmatched (incl. key 0) -> 0
}

__global__ void __launch_bounds__(512)
uavid_vec4_f32_kernel(const int4* __restrict__ rp,
                      const int4* __restrict__ gp,
                      const int4* __restrict__ bp,
                      float4* __restrict__ out,
                      int n4) {
    int i = blockIdx.x * blockDim.x + threadIdx.x;
    if (i >= n4) return;
    int4 r = rp[i];
    int4 g = gp[i];
    int4 b = bp[i];
    float4 o;
    o.x = classify(r.x, g.x, b.x);
    o.y = classify(r.y, g.y, b.y);
    o.z = classify(r.z, g.z, b.z);
    o.w = classify(r.w, g.w, b.w);
    out[i] = o;
}

__global__ void uavid_tail_f32_kernel(const int* __restrict__ rp,
                                      const int* __restrict__ gp,
                                      const int* __restrict__ bp,
                                      float* __restrict__ out,
                                      int start, int hw) {
    int i = start + blockIdx.x * blockDim.x + threadIdx.x;
    if (i >= hw) return;
    out[i] = classify(rp[i], gp[i], bp[i]);
}

extern "C" void kernel_launch(void* const* d_in, const int* in_sizes, int n_in,
                              void* d_out, int out_size) {
    const int* t = (const int*)d_in[0];
    int n  = in_sizes[0];     // 3 * H * W
    int hw = n / 3;           // H * W
    const int* rp = t;
    const int* gp = t + hw;
    const int* bp = t + 2 * hw;

    int n4  = hw >> 2;        // vectorized pixel-quads
    int rem = hw & 3;

    if (n4 > 0) {
        int threads = 512;
        int blocks  = (n4 + threads - 1) / threads;
        uavid_vec4_f32_kernel<<<blocks, threads>>>(
            (const int4*)rp, (const int4*)gp, (const int4*)bp,
            (float4*)d_out, n4);
    }
    if (rem > 0) {
        uavid_tail_f32_kernel<<<1, 256>>>(rp, gp, bp,
                                          (float*)d_out, n4 << 2, hw);
    }
}

// round 10
// speedup vs baseline: 1.0919x; 1.0014x over previous
#include <cuda_runtime.h>
#include <cstdint>

// UAVid palette -> class id, packed key (r<<16)|(g<<8)|b:
// 0: 0x000000  1: 0x800000  2: 0x804080  3: 0xC000C0
// 4: 0x008000  5: 0x808000  6: 0x404000  7: 0x400080
// Unmatched keys (incl. 0) -> class 0.

__device__ __forceinline__ float classify(int r, int g, int b) {
    unsigned key = ((unsigned)r << 16) | ((unsigned)g << 8) | (unsigned)b;
    int c = 0;
    c += (key == 0x800000u) ? 1 : 0;
    c += (key == 0x804080u) ? 2 : 0;
    c += (key == 0xC000C0u) ? 3 : 0;
    c += (key == 0x008000u) ? 4 : 0;
    c += (key == 0x808000u) ? 5 : 0;
    c += (key == 0x404000u) ? 6 : 0;
    c += (key == 0x400080u) ? 7 : 0;
    return (float)c;
}

// 4 pixels/thread: 3 coalesced int4 loads, 1 float4 store. Memory-roofline
// bound at ~5.75 TB/s DRAM (empirical ceiling for this R/W stream mix).
__global__ void __launch_bounds__(256)
uavid_vec4_f32_kernel(const int4* __restrict__ rp,
                      const int4* __restrict__ gp,
                      const int4* __restrict__ bp,
                      float4* __restrict__ out,
                      int n4) {
    int i = blockIdx.x * blockDim.x + threadIdx.x;
    if (i >= n4) return;
    int4 r = rp[i];
    int4 g = gp[i];
    int4 b = bp[i];
    float4 o;
    o.x = classify(r.x, g.x, b.x);
    o.y = classify(r.y, g.y, b.y);
    o.z = classify(r.z, g.z, b.z);
    o.w = classify(r.w, g.w, b.w);
    out[i] = o;
}

__global__ void uavid_tail_f32_kernel(const int* __restrict__ rp,
                                      const int* __restrict__ gp,
                                      const int* __restrict__ bp,
                                      float* __restrict__ out,
                                      int start, int hw) {
    int i = start + blockIdx.x * blockDim.x + threadIdx.x;
    if (i >= hw) return;
    out[i] = classify(rp[i], gp[i], bp[i]);
}

extern "C" void kernel_launch(void* const* d_in, const int* in_sizes, int n_in,
                              void* d_out, int out_size) {
    const int* t = (const int*)d_in[0];
    int n  = in_sizes[0];     // 3 * H * W
    int hw = n / 3;           // H * W
    const int* rp = t;
    const int* gp = t + hw;
    const int* bp = t + 2 * hw;

    int n4  = hw >> 2;        // pixel-quads
    int rem = hw & 3;

    if (n4 > 0) {
        int threads = 256;
        int blocks  = (n4 + threads - 1) / threads;
        uavid_vec4_f32_kernel<<<blocks, threads>>>(
            (const int4*)rp, (const int4*)gp, (const int4*)bp,
            (float4*)d_out, n4);
    }
    if (rem > 0) {
        uavid_tail_f32_kernel<<<1, 256>>>(rp, gp, bp,
                                          (float*)d_out, n4 << 2, hw);
    }
}